// round 14
// baseline (speedup 1.0000x reference)
#include <cuda_runtime.h>

// R2Ntab: out[b] = (# rules r with h[b,r] > 0.999999) * [w_or>0] + b_or,
// h[b,r] = x_b . rw_r + b_and[r] - relu(rw_r).sum(), rw = w_and masked by
// w_cancel<0 columns. x binary {0,1} => pass <=> deficit(sum |w| over
// mismatched care features) < eps_r = b_and[r]-0.999999 => 256-bit pattern
// match (x_bits & care_r) == pos_r when all care weights have |w| >= eps.
//
// R14: word w = features [32w,32w+32); per-warp screening word g = gw&7.
// NEW: 16-feature (64B) screen, TWO rows per LDG: lanes 0-15 read 64B of
// row A, lanes 16-31 of row B; one ballot = both rows' 16-bit signatures;
// per-lane 4-rule check on the word-g low-half masks. Halves DRAM bytes
// (sector-granular fills) and instructions/row; line count unchanged.
// Survivors (~1/512 of rows, data-dependent) get the exact full 8-word
// check; exact-flagged rules force the full path. Correct for any data.

#define FDIM 256
#define RDIM 128
#define PAIRS 16                     // LDGs per chunk; 2 rows each -> 32 rows
#define NTHREADS 256
#define NBLOCKS 512
#define FULLM 0xffffffffu

__device__ unsigned g_pos[8][RDIM];
__device__ unsigned g_care[8][RDIM];
__device__ float    g_thresh[RDIM];
__device__ float    g_rw[RDIM * FDIM];
__device__ int      g_exact_flag[RDIM];

// ---------------------------------------------------------------------------
// Prep: one warp per rule (16 blocks x 256). Word w bit j <-> feature 32w+j.
// ---------------------------------------------------------------------------
__global__ void prep_kernel(const float* __restrict__ wc,
                            const float* __restrict__ wa,
                            const float* __restrict__ ba,
                            const float* __restrict__ wo) {
    int gt   = blockIdx.x * blockDim.x + threadIdx.x;
    int r    = gt >> 5;
    int lane = gt & 31;
    if (r >= RDIM) return;

    float eps     = ba[r] - 0.999999f;
    bool  include = wo[r] > 0.0f;

    float relu_sum = 0.f, sum_tiny = 0.f;
    unsigned pos[8], care[8];
#pragma unroll
    for (int w = 0; w < 8; w++) {
        int   f  = 32 * w + lane;
        float wv = (wc[f] < 0.f) ? 0.f : wa[r * FDIM + f];
        g_rw[r * FDIM + f] = wv;
        relu_sum += fmaxf(wv, 0.f);
        float aw   = fabsf(wv);
        bool  must = (aw >= eps);
        if (!must) sum_tiny += aw;
        pos[w]  = __ballot_sync(FULLM, must && (wv > 0.f));
        care[w] = __ballot_sync(FULLM, must && (wv != 0.f));
    }
#pragma unroll
    for (int o = 16; o; o >>= 1) {
        relu_sum += __shfl_xor_sync(FULLM, relu_sum, o);
        sum_tiny += __shfl_xor_sync(FULLM, sum_tiny, o);
    }

    bool afalse = (!include) || (eps <= 0.f);
    bool exact  = (!afalse) && (sum_tiny >= eps);
    if (afalse || exact) {
        // Impossible at EVERY word: (x & 0) ^ 0xFFFFFFFF != 0 always,
        // so any screen (including 16-bit halves) rejects these rules.
#pragma unroll
        for (int w = 0; w < 8; w++) { pos[w] = 0xFFFFFFFFu; care[w] = 0u; }
    }
    if (lane == 0) {
        g_thresh[r]     = relu_sum - eps;
        g_exact_flag[r] = exact ? 1 : 0;
#pragma unroll
        for (int w = 0; w < 8; w++) { g_pos[w][r] = pos[w]; g_care[w][r] = care[w]; }
    }
}

// ---------------------------------------------------------------------------
// Main: warp per 32-row chunk. Per LDG.32: lanes 0-15 = 64B of row A,
// lanes 16-31 = 64B of row B (features [32g, 32g+16)). One ballot -> two
// 16-bit signatures; per-lane 4-rule half-mask check; REDUX row mask;
// one coalesced 32-lane reject store. Survivors -> full 8-word check.
// ---------------------------------------------------------------------------
__global__ void __launch_bounds__(NTHREADS, 5)
main_kernel(const float* __restrict__ x,
            const float* __restrict__ bor,
            float* __restrict__ out, int B) {
    __shared__ unsigned s_pos[8][RDIM];
    __shared__ unsigned s_care[8][RDIM];
    __shared__ int s_nx;
    __shared__ int s_xr[RDIM];

    const int tid = threadIdx.x;
    if (tid == 0) s_nx = 0;
    __syncthreads();
    for (int i = tid; i < 8 * RDIM; i += NTHREADS) {
        (&s_pos[0][0])[i]  = (&g_pos[0][0])[i];
        (&s_care[0][0])[i] = (&g_care[0][0])[i];
    }
    if (tid < RDIM && g_exact_flag[tid]) {
        int i = atomicAdd(&s_nx, 1);
        s_xr[i] = tid;
    }
    __syncthreads();

    const int   lane = tid & 31;
    const int   nx   = s_nx;
    const float b0   = bor[0];

    const int gw = blockIdx.x * (NTHREADS >> 5) + (tid >> 5);
    const int nw = gridDim.x * (NTHREADS >> 5);
    const int g  = gw & 7;                 // this warp's screening word

    // 16-bit (low-half of word g) masks for this lane's 4 rules.
    unsigned pg[4], cg[4];
#pragma unroll
    for (int k = 0; k < 4; k++) {
        pg[k] = s_pos[g][lane + 32 * k] & 0xFFFFu;
        cg[k] = s_care[g][lane + 32 * k] & 0xFFFFu;
    }

    const int nchunks = B >> 5;            // 32 rows per chunk

    // Full (rare) evaluation of one row: read all 8 words, exact check.
    auto full_row = [&](int row) {
        unsigned xw[8];
#pragma unroll
        for (int w = 0; w < 8; w++) {
            float v = x[(size_t)row * FDIM + 32 * w + lane];
            xw[w] = __ballot_sync(FULLM, v > 0.5f);
        }
        int cnt = 0;
#pragma unroll
        for (int k = 0; k < 4; k++) {
            int r = lane + 32 * k;
            unsigned acc = 0u;
#pragma unroll
            for (int w = 0; w < 8; w++)
                acc |= (xw[w] & s_care[w][r]) ^ s_pos[w][r];
            if (acc == 0u) cnt++;
        }
        for (int e = 0; e < nx; e++) {             // exact fp32 fallback
            int r = s_xr[e];
            float s = 0.f;
#pragma unroll
            for (int w = 0; w < 8; w++) {
                if ((xw[w] >> lane) & 1u)
                    s += g_rw[r * FDIM + 32 * w + lane];
            }
#pragma unroll
            for (int o = 16; o; o >>= 1)
                s += __shfl_xor_sync(FULLM, s, o);
            if (lane == 0 && s > g_thresh[r]) cnt++;
        }
#pragma unroll
        for (int o = 16; o; o >>= 1)
            cnt += __shfl_xor_sync(FULLM, cnt, o);
        if (lane == 0) out[row] = (float)cnt + b0;
    };

    // Per-lane fixed offset: row parity (A/B) + feature 32g + (lane&15).
    const size_t lane_off = (size_t)(lane >> 4) * FDIM + 32 * g + (lane & 15);

    for (int ch = gw; ch < nchunks; ch += nw) {
        int row0 = ch << 5;

        // 16 independent LDG.32; LDG u covers rows row0+2u (A) / row0+2u+1 (B).
        float v[PAIRS];
        const float* base = x + (size_t)row0 * FDIM + lane_off;
#pragma unroll
        for (int u = 0; u < PAIRS; u++)
            v[u] = base[(size_t)(2 * u) * FDIM];

        unsigned candm = 0u;
#pragma unroll
        for (int u = 0; u < PAIRS; u++) {
            unsigned xw = __ballot_sync(FULLM, v[u] > 0.5f);
            unsigned bA = xw & 0xFFFFu;            // row A's 16-bit signature
            unsigned bB = xw >> 16;                // row B's
            bool cA = false, cB = false;
#pragma unroll
            for (int k = 0; k < 4; k++) {
                cA |= (((bA & cg[k]) ^ pg[k]) == 0u);
                cB |= (((bB & cg[k]) ^ pg[k]) == 0u);
            }
            candm |= (((unsigned)cA) << (2 * u)) | (((unsigned)cB) << (2 * u + 1));
        }
        unsigned m = __reduce_or_sync(FULLM, candm);
        if (nx) m = 0xFFFFFFFFu;                   // exact rules: all rows full

        // Coalesced 32-lane store for rejected rows (the ~always case).
        if (!((m >> lane) & 1u))
            out[row0 + lane] = b0;

        while (m) {                                // warp-uniform, rare
            int j = __ffs(m) - 1;
            m &= m - 1;
            full_row(row0 + j);
        }
    }

    // Tail rows (B not divisible by 32; not hit for B = 131072).
    for (int row = (nchunks << 5) + gw; row < B; row += nw)
        full_row(row);
}

extern "C" void kernel_launch(void* const* d_in, const int* in_sizes, int n_in,
                              void* d_out, int out_size) {
    const float* x  = (const float*)d_in[0];   // [B, 256] binary
    const float* wc = (const float*)d_in[1];   // [256]
    const float* wa = (const float*)d_in[2];   // [128, 256]
    const float* ba = (const float*)d_in[3];   // [128]
    const float* wo = (const float*)d_in[4];   // [1, 128]
    const float* bo = (const float*)d_in[5];   // [1]
    float* out = (float*)d_out;

    int B = in_sizes[0] / FDIM;

    prep_kernel<<<16, 256>>>(wc, wa, ba, wo);      // 128 warps, 1 per rule
    main_kernel<<<NBLOCKS, NTHREADS>>>(x, bo, out, B);
}

// round 15
// speedup vs baseline: 2.2328x; 2.2328x over previous
#include <cuda_runtime.h>
#include <cuda.h>

// R2Ntab: out[b] = (# rules r with h[b,r] > 0.999999) * [w_or>0] + b_or,
// h[b,r] = x_b . rw_r + b_and[r] - relu(rw_r).sum(), rw = w_and masked by
// w_cancel<0 columns. x binary {0,1} => pass <=> 256-bit pattern match
// (x_bits & care_r) == pos_r when all care weights have |w| >= eps
// (= b_and[r]-0.999999); tiny weights -> don't-care or exact fallback.
//
// R15: screening fetches go through the TMA engine. A 2D tensor map views
// x as {256 floats, B rows} with 1KB row stride; box {32, 128} gathers 128
// rows' 128B word-g segments per UTMALDG into SMEM. This bypasses the
// per-SM L1tex MSHR cap (~32 outstanding lines) that pinned every LDG
// variant at ~11 lines/ns. One CTA per 128-row tile; survivors of the
// word-g screen get the exact full 8-word check from global memory.
// If the driver entry point for tensor-map creation is unavailable, falls
// back to the proven R12 LDG kernel.

#define FDIM 256
#define RDIM 128
#define TILE_ROWS 128
#define SEG 32                          // floats per screening segment
#define TILE_BYTES (TILE_ROWS * SEG * 4)   // 16384
#define FULLM 0xffffffffu
// fallback kernel config
#define UNROLL 16
#define FB_NTHREADS 256
#define FB_NBLOCKS 740

__device__ unsigned g_pos[8][RDIM];
__device__ unsigned g_care[8][RDIM];
__device__ float    g_thresh[RDIM];
__device__ float    g_rw[RDIM * FDIM];
__device__ int      g_exact_flag[RDIM];

// ---------------------------------------------------------------------------
// PTX helpers
// ---------------------------------------------------------------------------
__device__ __forceinline__ unsigned smem_u32(const void* p) {
    unsigned a;
    asm("{ .reg .u64 t; cvta.to.shared.u64 t, %1; cvt.u32.u64 %0, t; }"
        : "=r"(a) : "l"(p));
    return a;
}
#define MBAR_INIT(addr, cnt) \
    asm volatile("mbarrier.init.shared.b64 [%0], %1;" :: "r"(addr), "r"(cnt) : "memory")
#define MBAR_EXPECT_TX(addr, bytes) \
    asm volatile("mbarrier.arrive.expect_tx.shared.b64 _, [%0], %1;" \
                 :: "r"(addr), "r"(bytes) : "memory")
#define TMA_LOAD_2D(smem, tmapp, c0, c1, mbar) \
    asm volatile("cp.async.bulk.tensor.2d.shared::cta.global.tile.mbarrier::complete_tx::bytes " \
                 "[%0], [%1, {%2, %3}], [%4];" \
                 :: "r"(smem), "l"(tmapp), "r"(c0), "r"(c1), "r"(mbar) : "memory")
__device__ __forceinline__ void mbar_wait(unsigned mbar, unsigned parity) {
    unsigned done;
    asm volatile(
        "{\n\t.reg .pred p;\n\t"
        "mbarrier.try_wait.parity.acquire.cta.shared::cta.b64 p, [%1], %2;\n\t"
        "selp.b32 %0, 1, 0, p;\n\t}"
        : "=r"(done) : "r"(mbar), "r"(parity) : "memory");
    if (!done) {
        asm volatile(
            "{\n\t.reg .pred P1;\n\t"
            "WL_%=:\n\t"
            "mbarrier.try_wait.parity.acquire.cta.shared::cta.b64 P1, [%0], %1, 0x989680;\n\t"
            "@P1 bra.uni WD_%=;\n\t"
            "bra.uni WL_%=;\n\t"
            "WD_%=:\n\t}"
            :: "r"(mbar), "r"(parity) : "memory");
    }
}

// ---------------------------------------------------------------------------
// Prep: one warp per rule. Word w bit j <-> feature 32w + j.
// ---------------------------------------------------------------------------
__global__ void prep_kernel(const float* __restrict__ wc,
                            const float* __restrict__ wa,
                            const float* __restrict__ ba,
                            const float* __restrict__ wo) {
    int gt   = blockIdx.x * blockDim.x + threadIdx.x;
    int r    = gt >> 5;
    int lane = gt & 31;
    if (r >= RDIM) return;

    float eps     = ba[r] - 0.999999f;
    bool  include = wo[r] > 0.0f;

    float relu_sum = 0.f, sum_tiny = 0.f;
    unsigned pos[8], care[8];
#pragma unroll
    for (int w = 0; w < 8; w++) {
        int   f  = 32 * w + lane;
        float wv = (wc[f] < 0.f) ? 0.f : wa[r * FDIM + f];
        g_rw[r * FDIM + f] = wv;
        relu_sum += fmaxf(wv, 0.f);
        float aw   = fabsf(wv);
        bool  must = (aw >= eps);
        if (!must) sum_tiny += aw;
        pos[w]  = __ballot_sync(FULLM, must && (wv > 0.f));
        care[w] = __ballot_sync(FULLM, must && (wv != 0.f));
    }
#pragma unroll
    for (int o = 16; o; o >>= 1) {
        relu_sum += __shfl_xor_sync(FULLM, relu_sum, o);
        sum_tiny += __shfl_xor_sync(FULLM, sum_tiny, o);
    }

    bool afalse = (!include) || (eps <= 0.f);
    bool exact  = (!afalse) && (sum_tiny >= eps);
    if (afalse || exact) {
        // Impossible at EVERY word: (x & 0) ^ 0xFFFFFFFF != 0 always.
#pragma unroll
        for (int w = 0; w < 8; w++) { pos[w] = 0xFFFFFFFFu; care[w] = 0u; }
    }
    if (lane == 0) {
        g_thresh[r]     = relu_sum - eps;
        g_exact_flag[r] = exact ? 1 : 0;
#pragma unroll
        for (int w = 0; w < 8; w++) { g_pos[w][r] = pos[w]; g_care[w][r] = care[w]; }
    }
}

// ---------------------------------------------------------------------------
// Shared full-row evaluator (rare path): exact 8-word check + fp32 fallback.
// Masks read from global (L2-hot). Warp-collective.
// ---------------------------------------------------------------------------
__device__ __forceinline__ void full_row_eval(
    const float* __restrict__ x, float* __restrict__ out,
    int row, int lane, int nx, const int* s_xr, float b0) {
    unsigned xw[8];
#pragma unroll
    for (int w = 0; w < 8; w++) {
        float v = x[(size_t)row * FDIM + 32 * w + lane];
        xw[w] = __ballot_sync(FULLM, v > 0.5f);
    }
    int cnt = 0;
#pragma unroll
    for (int k = 0; k < 4; k++) {
        int r = lane + 32 * k;
        unsigned acc = 0u;
#pragma unroll
        for (int w = 0; w < 8; w++)
            acc |= (xw[w] & g_care[w][r]) ^ g_pos[w][r];
        if (acc == 0u) cnt++;
    }
    for (int e = 0; e < nx; e++) {              // exact fp32 fallback
        int r = s_xr[e];
        float s = 0.f;
#pragma unroll
        for (int w = 0; w < 8; w++) {
            if ((xw[w] >> lane) & 1u)
                s += g_rw[r * FDIM + 32 * w + lane];
        }
#pragma unroll
        for (int o = 16; o; o >>= 1)
            s += __shfl_xor_sync(FULLM, s, o);
        if (lane == 0 && s > g_thresh[r]) cnt++;
    }
#pragma unroll
    for (int o = 16; o; o >>= 1)
        cnt += __shfl_xor_sync(FULLM, cnt, o);
    if (lane == 0) out[row] = (float)cnt + b0;
}

// ---------------------------------------------------------------------------
// TMA main: one CTA per 128-row tile. UTMALDG gathers 128 x 128B word-g
// segments into SMEM; 8 warps screen 16 rows each from SMEM.
// ---------------------------------------------------------------------------
__global__ void __launch_bounds__(256)
main_tma(const __grid_constant__ CUtensorMap tmap,
         const float* __restrict__ x,
         const float* __restrict__ bor,
         float* __restrict__ out, int B) {
    __shared__ __align__(1024) float s_tile[TILE_ROWS * SEG];
    __shared__ __align__(8) unsigned long long s_mbar;
    __shared__ int s_nx;
    __shared__ int s_xr[RDIM];

    const int tid  = threadIdx.x;
    const int lane = tid & 31;
    const int wid  = tid >> 5;
    const int tile = blockIdx.x;
    const int g    = tile & 7;              // this tile's screening word
    const int row0t = tile * TILE_ROWS;

    if (tid == 0) {
        s_nx = 0;
        MBAR_INIT(smem_u32(&s_mbar), 1);
    }
    __syncthreads();

    if (tid == 0) {                          // issue the gather immediately
        unsigned mb = smem_u32(&s_mbar);
        MBAR_EXPECT_TX(mb, TILE_BYTES);
        TMA_LOAD_2D(smem_u32(s_tile), &tmap, SEG * g, row0t, mb);
    }

    // Overlap: exact-flag scan + screening masks while TMA flies.
    if (tid < RDIM && g_exact_flag[tid]) {
        int i = atomicAdd(&s_nx, 1);
        s_xr[i] = tid;
    }
    unsigned pg[4], cg[4];
#pragma unroll
    for (int k = 0; k < 4; k++) {
        pg[k] = g_pos[g][lane + 32 * k];
        cg[k] = g_care[g][lane + 32 * k];
    }
    __syncthreads();                         // s_nx/s_xr ready
    const int   nx = s_nx;
    const float b0 = bor[0];

    mbar_wait(smem_u32(&s_mbar), 0);

    // Screen: warp wid handles tile rows [wid*16, wid*16+16).
    const int rbase = wid * 16;
    float v[16];
#pragma unroll
    for (int u = 0; u < 16; u++)
        v[u] = s_tile[(rbase + u) * SEG + lane];

    unsigned candm = 0u;
#pragma unroll
    for (int u = 0; u < 16; u++) {
        unsigned xw = __ballot_sync(FULLM, v[u] > 0.5f);
        bool cand = false;
#pragma unroll
        for (int k = 0; k < 4; k++)
            cand |= (((xw & cg[k]) ^ pg[k]) == 0u);
        candm |= ((unsigned)cand) << u;
    }
    unsigned m = __reduce_or_sync(FULLM, candm);
    if (nx) m = 0xFFFFu;                     // exact rules: all rows full

    const int grow0 = row0t + rbase;
    if (lane < 16) {
        int row = grow0 + lane;
        if (row < B && !((m >> lane) & 1u)) out[row] = b0;
    }
    while (m) {                              // warp-uniform, rare
        int j = __ffs(m) - 1;
        m &= m - 1;
        int row = grow0 + j;
        if (row < B) full_row_eval(x, out, row, lane, nx, s_xr, b0);
    }
}

// ---------------------------------------------------------------------------
// Fallback main (R12, proven 12.0us): LDG screen, per-warp word g.
// ---------------------------------------------------------------------------
__global__ void __launch_bounds__(FB_NTHREADS, 5)
main_ldg(const float* __restrict__ x,
         const float* __restrict__ bor,
         float* __restrict__ out, int B) {
    __shared__ int s_nx;
    __shared__ int s_xr[RDIM];

    const int tid = threadIdx.x;
    if (tid == 0) s_nx = 0;
    __syncthreads();
    if (tid < RDIM && g_exact_flag[tid]) {
        int i = atomicAdd(&s_nx, 1);
        s_xr[i] = tid;
    }
    __syncthreads();

    const int   lane = tid & 31;
    const int   nx   = s_nx;
    const float b0   = bor[0];

    const int gw = blockIdx.x * (FB_NTHREADS >> 5) + (tid >> 5);
    const int nw = gridDim.x * (FB_NTHREADS >> 5);
    const int g  = gw & 7;

    unsigned pg[4], cg[4];
#pragma unroll
    for (int k = 0; k < 4; k++) {
        pg[k] = g_pos[g][lane + 32 * k];
        cg[k] = g_care[g][lane + 32 * k];
    }

    const int nchunks = B / UNROLL;
    for (int ch = gw; ch < nchunks; ch += nw) {
        int row0 = ch * UNROLL;
        float v[UNROLL];
#pragma unroll
        for (int u = 0; u < UNROLL; u++)
            v[u] = x[(size_t)(row0 + u) * FDIM + 32 * g + lane];
        unsigned candm = 0u;
#pragma unroll
        for (int u = 0; u < UNROLL; u++) {
            unsigned xw = __ballot_sync(FULLM, v[u] > 0.5f);
            bool cand = false;
#pragma unroll
            for (int k = 0; k < 4; k++)
                cand |= (((xw & cg[k]) ^ pg[k]) == 0u);
            candm |= ((unsigned)cand) << u;
        }
        unsigned m = __reduce_or_sync(FULLM, candm);
        if (nx) m = (1u << UNROLL) - 1u;
        if (lane < UNROLL && !((m >> lane) & 1u))
            out[row0 + lane] = b0;
        while (m) {
            int j = __ffs(m) - 1;
            m &= m - 1;
            full_row_eval(x, out, row0 + j, lane, nx, s_xr, b0);
        }
    }
    for (int row = nchunks * UNROLL + gw; row < B; row += nw)
        full_row_eval(x, out, row, lane, nx, s_xr, b0);
}

// ---------------------------------------------------------------------------
// Host
// ---------------------------------------------------------------------------
typedef CUresult (*EncodeTiledFn)(
    CUtensorMap*, CUtensorMapDataType, cuuint32_t, void*,
    const cuuint64_t*, const cuuint64_t*, const cuuint32_t*, const cuuint32_t*,
    CUtensorMapInterleave, CUtensorMapSwizzle, CUtensorMapL2promotion,
    CUtensorMapFloatOOBfill);

extern "C" void kernel_launch(void* const* d_in, const int* in_sizes, int n_in,
                              void* d_out, int out_size) {
    const float* x  = (const float*)d_in[0];   // [B, 256] binary
    const float* wc = (const float*)d_in[1];   // [256]
    const float* wa = (const float*)d_in[2];   // [128, 256]
    const float* ba = (const float*)d_in[3];   // [128]
    const float* wo = (const float*)d_in[4];   // [1, 128]
    const float* bo = (const float*)d_in[5];   // [1]
    float* out = (float*)d_out;

    int B = in_sizes[0] / FDIM;

    prep_kernel<<<16, 256>>>(wc, wa, ba, wo);  // 128 warps, 1 per rule

    // Resolve cuTensorMapEncodeTiled through the runtime (no -lcuda dep).
    void* fp = nullptr;
    cudaDriverEntryPointQueryResult qr = cudaDriverEntryPointSymbolNotFound;
    cudaGetDriverEntryPointByVersion("cuTensorMapEncodeTiled", &fp, 12000,
                                     cudaEnableDefault, &qr);
    bool tma_ok = (qr == cudaDriverEntryPointSuccess) && fp;

    CUtensorMap tmap;
    if (tma_ok) {
        cuuint64_t dims[2]    = {(cuuint64_t)FDIM, (cuuint64_t)B};
        cuuint64_t strides[1] = {(cuuint64_t)FDIM * 4};
        cuuint32_t box[2]     = {SEG, TILE_ROWS};
        cuuint32_t estr[2]    = {1, 1};
        CUresult r = ((EncodeTiledFn)fp)(
            &tmap, CU_TENSOR_MAP_DATA_TYPE_FLOAT32, 2, (void*)x,
            dims, strides, box, estr,
            CU_TENSOR_MAP_INTERLEAVE_NONE, CU_TENSOR_MAP_SWIZZLE_NONE,
            CU_TENSOR_MAP_L2_PROMOTION_L2_128B,
            CU_TENSOR_MAP_FLOAT_OOB_FILL_NONE);
        tma_ok = (r == CUDA_SUCCESS);
    }

    if (tma_ok) {
        int ntiles = (B + TILE_ROWS - 1) / TILE_ROWS;
        main_tma<<<ntiles, 256>>>(tmap, x, bo, out, B);
    } else {
        main_ldg<<<FB_NBLOCKS, FB_NTHREADS>>>(x, bo, out, B);
    }
}